// round 7
// baseline (speedup 1.0000x reference)
#include <cuda_runtime.h>
#include <cuda_bf16.h>
#include <cuda_fp8.h>
#include <cstdint>
#include <math.h>

#define N2     4096
#define D      512
#define HALF_N 2048
#define NTILE  32
#define NBLK   528           // upper-triangular tiles
#define NCTA   264           // 2 tiles per CTA; == one 2-CTA/SM residency wave
#define NPART  96            // slots/row: 64 direct + 32 transposed
#define ALPHA  1.69864360f   // sqrt(2*log2 e)
#define QS     32.0f
#define SCI    (1.0f / 1024.0f)
#define LN2S   (0.69314718056f / 1024.0f)

__device__ uint8_t g_xq[N2 * D];         // normalized, alpha*32-scaled e4m3 (2 MB)
__device__ float g_part[N2 * NPART];     // zero-init; unwritten slots stay 0
__device__ float g_pos[N2];
__device__ double g_blk[NCTA];
__device__ int g_rdy[NTILE];             // per-128-row-block arrival counters (8 each)
__device__ int g_done, g_done2;          // grid-sync counters (self-resetting)

__device__ __forceinline__ uint32_t smem_u32(const void* p) {
    uint32_t a;
    asm("{ .reg .u64 t; cvta.to.shared.u64 t, %1; cvt.u32.u64 %0, t; }" : "=r"(a) : "l"(p));
    return a;
}
__device__ __forceinline__ float ex2f(float x) {
    float y; asm("ex2.approx.f32 %0, %1;" : "=f"(y) : "f"(x)); return y;
}

#define CP16(sm, gm)  asm volatile("cp.async.cg.shared.global [%0], [%1], 16;" :: "r"(sm), "l"(gm) : "memory")
#define CP_COMMIT()   asm volatile("cp.async.commit_group;" ::: "memory")
#define CP_WAIT1()    asm volatile("cp.async.wait_group 1;" ::: "memory")
#define CP_WAIT0()    asm volatile("cp.async.wait_group 0;" ::: "memory")

#define LDSM_X4(r0, r1, r2, r3, addr)                                         \
    asm volatile("ldmatrix.sync.aligned.m8n8.x4.shared.b16 {%0,%1,%2,%3}, [%4];" \
        : "=r"(r0), "=r"(r1), "=r"(r2), "=r"(r3) : "r"(addr))

#define MMAFP8(c, a, b0, b1)                                                  \
    asm volatile("mma.sync.aligned.m16n8k32.row.col.f32.e4m3.e4m3.f32 "       \
        "{%0,%1,%2,%3}, {%4,%5,%6,%7}, {%8,%9}, {%0,%1,%2,%3};"               \
        : "+f"((c)[0]), "+f"((c)[1]), "+f"((c)[2]), "+f"((c)[3])              \
        : "r"((a)[0]), "r"((a)[1]), "r"((a)[2]), "r"((a)[3]), "r"(b0), "r"(b1))

#define TILE_B     16384
#define STAGE_B    32768
#define SMEM_TOTAL (1024 + 3 * STAGE_B)

__global__ void __launch_bounds__(256, 2) fused_kernel(const float* __restrict__ x,
                                                       float* __restrict__ out) {
    extern __shared__ char smem_raw[];
    uint32_t tiles = (smem_u32(smem_raw) + 1023) & ~1023u;
    float* cs_smem = reinterpret_cast<float*>(smem_raw) +
                     ((tiles - smem_u32(smem_raw)) >> 2);

    const int cta = blockIdx.x;
    const int tid = threadIdx.x, wid = tid >> 5, lane = tid & 31;
    const int wr = wid & 3, wc = wid >> 2;

    // ===================== Phase 1: norm (CTAs 0..255, 16 rows each) ========
    if (cta < 256) {
        #pragma unroll
        for (int rr = 0; rr < 2; rr++) {
            int row = cta * 16 + wid * 2 + rr;
            const float4* xr = reinterpret_cast<const float4*>(x + (size_t)row * D);
            float4 v[4];
            float ss = 0.0f;
            #pragma unroll
            for (int i = 0; i < 4; i++) {
                v[i] = xr[lane + 32 * i];
                ss += v[i].x * v[i].x + v[i].y * v[i].y + v[i].z * v[i].z + v[i].w * v[i].w;
            }
            #pragma unroll
            for (int o = 16; o; o >>= 1) ss += __shfl_xor_sync(0xffffffffu, ss, o);
            float inv = (ALPHA * QS) / fmaxf(sqrtf(ss), 1e-8f);
            uint32_t* orow = reinterpret_cast<uint32_t*>(g_xq + (size_t)row * D);
            #pragma unroll
            for (int i = 0; i < 4; i++) {
                uint32_t lo = __nv_cvt_float2_to_fp8x2(make_float2(v[i].x * inv, v[i].y * inv),
                                                       __NV_SATFINITE, __NV_E4M3);
                uint32_t hi = __nv_cvt_float2_to_fp8x2(make_float2(v[i].z * inv, v[i].w * inv),
                                                       __NV_SATFINITE, __NV_E4M3);
                orow[lane + 32 * i] = lo | (hi << 16);
            }
        }
        __syncthreads();
        if (tid == 0) { __threadfence(); atomicAdd(&g_rdy[cta >> 3], 1); }
    }

    // ===================== Phase 2: GEMM (2 triangle tiles per CTA) =========
    const int lr8   = lane & 7;
    const int rin16 = lr8 + ((lane >> 3) & 1) * 8;
    const int hioff = ((lane >> 4) & 1) * 16;
    const uint32_t rx = (uint32_t)lr8 << 4;
    const uint32_t offA0 = (uint32_t)(wr * 32 + rin16) * 128;
    const uint32_t offB0 = (uint32_t)(wc * 64 + rin16) * 128;

    const int rb = tid >> 3;
    const int klo = (tid & 7) * 16;
    uint32_t swo[4];
    #pragma unroll
    for (int p = 0; p < 4; p++) {
        int row = rb + 32 * p;
        swo[p] = (uint32_t)row * 128 + ((uint32_t)klo ^ ((uint32_t)(row & 7) << 4));
    }

    #pragma unroll 1
    for (int half = 0; half < 2; half++) {
        int b = cta * 2 + half, ti = 0;
        while (b >= NTILE - ti) { b -= NTILE - ti; ti++; }
        const int tj = ti + b;
        const int i0 = ti * 128, j0 = tj * 128;
        const bool diag = (ti == tj);
        const uint32_t sBoff = diag ? 0u : (uint32_t)TILE_B;

        // wait until both 128-row blocks are normalized
        if (tid == 0) {
            volatile int* rdy = g_rdy;
            while (rdy[ti] < 8 || rdy[tj] < 8) __nanosleep(32);
        }
        __syncthreads();

        const uint8_t *pA[4], *pB[4];
        #pragma unroll
        for (int p = 0; p < 4; p++) {
            int row = rb + 32 * p;
            pA[p] = g_xq + (size_t)(i0 + row) * D + klo;
            pB[p] = g_xq + (size_t)(j0 + row) * D + klo;
        }
        auto load_chunk = [&](int c, int s) {
            uint32_t bA = tiles + (uint32_t)s * STAGE_B;
            #pragma unroll
            for (int p = 0; p < 4; p++) CP16(bA + swo[p], pA[p] + c * 128);
            if (!diag) {
                uint32_t bB = bA + TILE_B;
                #pragma unroll
                for (int p = 0; p < 4; p++) CP16(bB + swo[p], pB[p] + c * 128);
            }
            CP_COMMIT();
        };

        float acc[2][8][4];
        #pragma unroll
        for (int mf = 0; mf < 2; mf++)
            #pragma unroll
            for (int nf = 0; nf < 8; nf++)
                #pragma unroll
                for (int e = 0; e < 4; e++) acc[mf][nf][e] = 0.0f;

        load_chunk(0, 0);
        load_chunk(1, 1);

        for (int c = 0; c < 4; c++) {
            if (c < 3) CP_WAIT1(); else CP_WAIT0();
            __syncthreads();
            if (c + 2 < 4) load_chunk(c + 2, (c + 2) % 3);

            uint32_t sA = tiles + (uint32_t)(c % 3) * STAGE_B;
            uint32_t sB = sA + sBoff;
            #pragma unroll
            for (int ks = 0; ks < 4; ks++) {
                uint32_t kx = ((uint32_t)(ks * 32) + hioff) ^ rx;
                uint32_t a[2][4], bb[4][4];
                #pragma unroll
                for (int mf = 0; mf < 2; mf++)
                    LDSM_X4(a[mf][0], a[mf][1], a[mf][2], a[mf][3],
                            sA + offA0 + (uint32_t)mf * 2048 + kx);
                #pragma unroll
                for (int p = 0; p < 4; p++)
                    LDSM_X4(bb[p][0], bb[p][1], bb[p][2], bb[p][3],
                            sB + offB0 + (uint32_t)p * 2048 + kx);
                #pragma unroll
                for (int mf = 0; mf < 2; mf++)
                    #pragma unroll
                    for (int nf = 0; nf < 8; nf++) {
                        int p = nf >> 1, h = nf & 1;
                        MMAFP8(acc[mf][nf], a[mf], bb[p][h], bb[p][h + 2]);
                    }
            }
        }
        __syncthreads();

        if (tj - ti == 16) {
            #pragma unroll
            for (int mf = 0; mf < 2; mf++)
                #pragma unroll
                for (int h = 0; h < 2; h++) {
                    int gi = i0 + wr * 32 + mf * 16 + (lane >> 2) + h * 8;
                    int pj = gi + HALF_N;
                    #pragma unroll
                    for (int nf = 0; nf < 8; nf++) {
                        int cb = j0 + wc * 64 + nf * 8 + (lane & 3) * 2;
                        if (cb == pj) {
                            float v = acc[mf][nf][2 * h] * LN2S;
                            g_pos[gi] = v; g_pos[pj & (N2 - 1)] = v;
                        }
                        if (cb + 1 == pj) {
                            float v = acc[mf][nf][2 * h + 1] * LN2S;
                            g_pos[gi] = v; g_pos[pj & (N2 - 1)] = v;
                        }
                    }
                }
        }

        #pragma unroll
        for (int mf = 0; mf < 2; mf++)
            #pragma unroll
            for (int nf = 0; nf < 8; nf++)
                #pragma unroll
                for (int e = 0; e < 4; e++) acc[mf][nf][e] = ex2f(acc[mf][nf][e] * SCI);

        #pragma unroll
        for (int mf = 0; mf < 2; mf++)
            #pragma unroll
            for (int h = 0; h < 2; h++) {
                float rs = 0.0f;
                #pragma unroll
                for (int nf = 0; nf < 8; nf++)
                    rs += acc[mf][nf][2 * h] + acc[mf][nf][2 * h + 1];
                rs += __shfl_xor_sync(0xffffffffu, rs, 1);
                rs += __shfl_xor_sync(0xffffffffu, rs, 2);
                if ((lane & 3) == 0) {
                    int gi = i0 + wr * 32 + mf * 16 + (lane >> 2) + h * 8;
                    g_part[(size_t)gi * NPART + tj * 2 + wc] = rs;
                }
            }

        if (!diag) {
            float cs[8][2];
            #pragma unroll
            for (int nf = 0; nf < 8; nf++) {
                cs[nf][0] = acc[0][nf][0] + acc[0][nf][2] + acc[1][nf][0] + acc[1][nf][2];
                cs[nf][1] = acc[0][nf][1] + acc[0][nf][3] + acc[1][nf][1] + acc[1][nf][3];
                #pragma unroll
                for (int o = 4; o <= 16; o <<= 1) {
                    cs[nf][0] += __shfl_xor_sync(0xffffffffu, cs[nf][0], o);
                    cs[nf][1] += __shfl_xor_sync(0xffffffffu, cs[nf][1], o);
                }
            }
            if (lane < 4) {
                #pragma unroll
                for (int nf = 0; nf < 8; nf++) {
                    cs_smem[wr * 128 + wc * 64 + nf * 8 + lane * 2]     = cs[nf][0];
                    cs_smem[wr * 128 + wc * 64 + nf * 8 + lane * 2 + 1] = cs[nf][1];
                }
            }
            __syncthreads();
            if (tid < 128) {
                float t = cs_smem[tid] + cs_smem[128 + tid] +
                          cs_smem[256 + tid] + cs_smem[384 + tid];
                g_part[(size_t)(j0 + tid) * NPART + 64 + ti] = t;
            }
        }
        __syncthreads();
    }

    // ===================== Phase 3: grid sync ===============================
    if (tid == 0) {
        __threadfence();
        atomicAdd(&g_done, 1);
        volatile int* dn = &g_done;
        while (*dn < NCTA) __nanosleep(64);
    }
    __syncthreads();
    __threadfence();

    // ===================== Phase 4: distributed finalize ====================
    {
        const float E2 = 7.38905609893065f;
        int r = cta * 16 + (tid >> 4);
        int sub = tid & 15;
        double d = 0.0;
        if (r < N2) {
            const float* pr = g_part + (size_t)r * NPART + sub * 6;
            float s = __ldcg(pr) + __ldcg(pr + 1) + __ldcg(pr + 2)
                    + __ldcg(pr + 3) + __ldcg(pr + 4) + __ldcg(pr + 5);
            #pragma unroll
            for (int o = 8; o; o >>= 1) s += __shfl_xor_sync(0xffffffffu, s, o);
            if (sub == 0) d = (double)(logf(s - E2) - __ldcg(&g_pos[r]));
        }
        // warp sum (only lanes 0 and 16 nonzero), then CTA sum
        #pragma unroll
        for (int o = 16; o; o >>= 1) d += __shfl_xor_sync(0xffffffffu, d, o);
        __shared__ double ws[8];
        __shared__ int islast;
        if (lane == 0) ws[wid] = d;
        __syncthreads();
        if (tid == 0) {
            double t = ws[0] + ws[1] + ws[2] + ws[3] + ws[4] + ws[5] + ws[6] + ws[7];
            g_blk[cta] = t;
            __threadfence();
            islast = (atomicAdd(&g_done2, 1) == NCTA - 1);
        }
        __syncthreads();
        if (islast) {
            double u = (tid < NCTA) ? __ldcg(&g_blk[tid]) : 0.0;
            if (tid < NCTA - 256) u += __ldcg(&g_blk[256 + tid]);
            #pragma unroll
            for (int o = 16; o; o >>= 1) u += __shfl_xor_sync(0xffffffffu, u, o);
            if (lane == 0) ws[wid] = u;
            __syncthreads();
            if (tid == 0) {
                double t = ws[0] + ws[1] + ws[2] + ws[3] + ws[4] + ws[5] + ws[6] + ws[7];
                out[0] = (float)(t / (double)N2);
                // reset all sync state for graph replay determinism
                #pragma unroll
                for (int i = 0; i < NTILE; i++) g_rdy[i] = 0;
                g_done = 0;
                g_done2 = 0;
            }
        }
    }
}

// ---------------------------------------------------------------------------
extern "C" void kernel_launch(void* const* d_in, const int* in_sizes, int n_in,
                              void* d_out, int out_size) {
    const float* x = (const float*)d_in[0];
    float* out = (float*)d_out;

    cudaFuncSetAttribute(fused_kernel,
                         cudaFuncAttributeMaxDynamicSharedMemorySize, SMEM_TOTAL);
    fused_kernel<<<NCTA, 256, SMEM_TOTAL>>>(x, out);
}

// round 8
// speedup vs baseline: 1.8064x; 1.8064x over previous
#include <cuda_runtime.h>
#include <cuda_bf16.h>
#include <cuda_fp8.h>
#include <cstdint>
#include <math.h>

#define N2     4096
#define D      512
#define HALF_N 2048
#define NTILE  32            // 4096/128 tiles per dim
#define NBLK   528           // upper-triangular tiles: 32*33/2
#define NPART  96            // slots/row: 64 direct (tj*2+wc) + 32 transposed (ti)
// sqrt(2*log2(e)): acc(unscaled) = 2*log2e*dot = log2(exp(sim)); fp8 adds x32 per side
#define ALPHA  1.69864360f
#define QS     32.0f
#define SCI    (1.0f / 1024.0f)            // 1/(QS*QS)
#define LN2S   (0.69314718056f / 1024.0f)

__device__ uint8_t g_xq[N2 * D];         // normalized, alpha*32-scaled e4m3 (2 MB)
__device__ float g_part[N2 * NPART];     // partial sums of exp (zero-init; unwritten slots stay 0)
__device__ float g_pos[N2];              // positive logit per row
__device__ double g_blk[16];             // per-block loss partials
__device__ int g_cnt;                    // finalize completion counter (self-resetting)

__device__ __forceinline__ uint32_t smem_u32(const void* p) {
    uint32_t a;
    asm("{ .reg .u64 t; cvta.to.shared.u64 t, %1; cvt.u32.u64 %0, t; }" : "=r"(a) : "l"(p));
    return a;
}
__device__ __forceinline__ float ex2f(float x) {
    float y; asm("ex2.approx.f32 %0, %1;" : "=f"(y) : "f"(x)); return y;
}

#define CP16(sm, gm)  asm volatile("cp.async.cg.shared.global [%0], [%1], 16;" :: "r"(sm), "l"(gm) : "memory")
#define CP_COMMIT()   asm volatile("cp.async.commit_group;" ::: "memory")
#define CP_WAIT1()    asm volatile("cp.async.wait_group 1;" ::: "memory")
#define CP_WAIT0()    asm volatile("cp.async.wait_group 0;" ::: "memory")

#define LDSM_X4(r0, r1, r2, r3, addr)                                         \
    asm volatile("ldmatrix.sync.aligned.m8n8.x4.shared.b16 {%0,%1,%2,%3}, [%4];" \
        : "=r"(r0), "=r"(r1), "=r"(r2), "=r"(r3) : "r"(addr))

// m16n8k32 e4m3: fragment byte-layout identical to m16n8k16 bf16
#define MMAFP8(c, a, b0, b1)                                                  \
    asm volatile("mma.sync.aligned.m16n8k32.row.col.f32.e4m3.e4m3.f32 "       \
        "{%0,%1,%2,%3}, {%4,%5,%6,%7}, {%8,%9}, {%0,%1,%2,%3};"               \
        : "+f"((c)[0]), "+f"((c)[1]), "+f"((c)[2]), "+f"((c)[3])              \
        : "r"((a)[0]), "r"((a)[1]), "r"((a)[2]), "r"((a)[3]), "r"(b0), "r"(b1))

// ---------------------------------------------------------------------------
// Kernel 1: 2 rows per warp (MLP 8), L2 norm (clamp 1e-8), e4m3 of xn*ALPHA*32
// ---------------------------------------------------------------------------
__global__ void __launch_bounds__(256) norm_kernel(const float* __restrict__ x) {
    int warp = threadIdx.x >> 5, lane = threadIdx.x & 31;
    int row0 = blockIdx.x * 16 + warp * 2;
    const float4* xr0 = reinterpret_cast<const float4*>(x + (size_t)row0 * D);
    const float4* xr1 = reinterpret_cast<const float4*>(x + (size_t)(row0 + 1) * D);
    float4 v0[4], v1[4];
    float s0 = 0.0f, s1 = 0.0f;
    #pragma unroll
    for (int i = 0; i < 4; i++) { v0[i] = xr0[lane + 32 * i]; }
    #pragma unroll
    for (int i = 0; i < 4; i++) { v1[i] = xr1[lane + 32 * i]; }
    #pragma unroll
    for (int i = 0; i < 4; i++) {
        s0 += v0[i].x * v0[i].x + v0[i].y * v0[i].y + v0[i].z * v0[i].z + v0[i].w * v0[i].w;
        s1 += v1[i].x * v1[i].x + v1[i].y * v1[i].y + v1[i].z * v1[i].z + v1[i].w * v1[i].w;
    }
    #pragma unroll
    for (int o = 16; o; o >>= 1) {
        s0 += __shfl_xor_sync(0xffffffffu, s0, o);
        s1 += __shfl_xor_sync(0xffffffffu, s1, o);
    }
    float i0 = (ALPHA * QS) / fmaxf(sqrtf(s0), 1e-8f);
    float i1 = (ALPHA * QS) / fmaxf(sqrtf(s1), 1e-8f);
    uint32_t* o0 = reinterpret_cast<uint32_t*>(g_xq + (size_t)row0 * D);
    uint32_t* o1 = reinterpret_cast<uint32_t*>(g_xq + (size_t)(row0 + 1) * D);
    #pragma unroll
    for (int i = 0; i < 4; i++) {
        uint32_t a = __nv_cvt_float2_to_fp8x2(make_float2(v0[i].x * i0, v0[i].y * i0),
                                              __NV_SATFINITE, __NV_E4M3);
        uint32_t b = __nv_cvt_float2_to_fp8x2(make_float2(v0[i].z * i0, v0[i].w * i0),
                                              __NV_SATFINITE, __NV_E4M3);
        o0[lane + 32 * i] = a | (b << 16);
        uint32_t c = __nv_cvt_float2_to_fp8x2(make_float2(v1[i].x * i1, v1[i].y * i1),
                                              __NV_SATFINITE, __NV_E4M3);
        uint32_t d = __nv_cvt_float2_to_fp8x2(make_float2(v1[i].z * i1, v1[i].w * i1),
                                              __NV_SATFINITE, __NV_E4M3);
        o1[lane + 32 * i] = c | (d << 16);
    }
}

// ---------------------------------------------------------------------------
// Kernel 2: persistent 2-tiles/CTA upper-triangle FP8 MMA + fused epilogue
// 256 thr, warps 4(m)x2(n), warp tile 32x64; BK=128 fp8 (128B rows), 4 chunks,
// 3-stage cp.async, SW128. Grid = 264 CTAs = one residency wave.
// ---------------------------------------------------------------------------
#define TILE_B     16384          // 128 rows x 128B (one matrix, one stage)
#define STAGE_B    32768          // A+B per stage
#define SMEM_TOTAL (1024 + 3 * STAGE_B)

__global__ void __launch_bounds__(256, 2) simexp_mma_kernel() {
    extern __shared__ char smem_raw[];
    uint32_t tiles = (smem_u32(smem_raw) + 1023) & ~1023u;
    float* cs_smem = reinterpret_cast<float*>(smem_raw) +
                     ((tiles - smem_u32(smem_raw)) >> 2);

    const int tid = threadIdx.x, wid = tid >> 5, lane = tid & 31;
    const int wr = wid & 3, wc = wid >> 2;

    // ldmatrix lane mapping (tile-independent)
    const int lr8   = lane & 7;
    const int rin16 = lr8 + ((lane >> 3) & 1) * 8;
    const int hioff = ((lane >> 4) & 1) * 16;
    const uint32_t rx = (uint32_t)lr8 << 4;
    const uint32_t offA0 = (uint32_t)(wr * 32 + rin16) * 128;
    const uint32_t offB0 = (uint32_t)(wc * 64 + rin16) * 128;

    // loader geometry: thread covers rows rb+32p, 16B at byte-col klo
    const int rb = tid >> 3;
    const int klo = (tid & 7) * 16;
    uint32_t swo[4];
    #pragma unroll
    for (int p = 0; p < 4; p++) {
        int row = rb + 32 * p;
        swo[p] = (uint32_t)row * 128 + ((uint32_t)klo ^ ((uint32_t)(row & 7) << 4));
    }

    #pragma unroll 1
    for (int half = 0; half < 2; half++) {
        int b = blockIdx.x * 2 + half, ti = 0;
        while (b >= NTILE - ti) { b -= NTILE - ti; ti++; }
        const int tj = ti + b;
        const int i0 = ti * 128, j0 = tj * 128;
        const bool diag = (ti == tj);
        const uint32_t sBoff = diag ? 0u : (uint32_t)TILE_B;

        const uint8_t *pA[4], *pB[4];
        #pragma unroll
        for (int p = 0; p < 4; p++) {
            int row = rb + 32 * p;
            pA[p] = g_xq + (size_t)(i0 + row) * D + klo;
            pB[p] = g_xq + (size_t)(j0 + row) * D + klo;
        }
        auto load_chunk = [&](int c, int s) {
            uint32_t bA = tiles + (uint32_t)s * STAGE_B;
            #pragma unroll
            for (int p = 0; p < 4; p++) CP16(bA + swo[p], pA[p] + c * 128);
            if (!diag) {
                uint32_t bB = bA + TILE_B;
                #pragma unroll
                for (int p = 0; p < 4; p++) CP16(bB + swo[p], pB[p] + c * 128);
            }
            CP_COMMIT();
        };

        float acc[2][8][4];
        #pragma unroll
        for (int mf = 0; mf < 2; mf++)
            #pragma unroll
            for (int nf = 0; nf < 8; nf++)
                #pragma unroll
                for (int e = 0; e < 4; e++) acc[mf][nf][e] = 0.0f;

        load_chunk(0, 0);
        load_chunk(1, 1);

        for (int c = 0; c < 4; c++) {
            if (c < 3) CP_WAIT1(); else CP_WAIT0();
            __syncthreads();
            if (c + 2 < 4) load_chunk(c + 2, (c + 2) % 3);

            uint32_t sA = tiles + (uint32_t)(c % 3) * STAGE_B;
            uint32_t sB = sA + sBoff;
            #pragma unroll
            for (int ks = 0; ks < 4; ks++) {            // 4 x k32 (32B) per 128B chunk
                uint32_t kx = ((uint32_t)(ks * 32) + hioff) ^ rx;
                uint32_t a[2][4], bb[4][4];
                #pragma unroll
                for (int mf = 0; mf < 2; mf++)
                    LDSM_X4(a[mf][0], a[mf][1], a[mf][2], a[mf][3],
                            sA + offA0 + (uint32_t)mf * 2048 + kx);
                #pragma unroll
                for (int p = 0; p < 4; p++)
                    LDSM_X4(bb[p][0], bb[p][1], bb[p][2], bb[p][3],
                            sB + offB0 + (uint32_t)p * 2048 + kx);
                #pragma unroll
                for (int mf = 0; mf < 2; mf++)
                    #pragma unroll
                    for (int nf = 0; nf < 8; nf++) {
                        int p = nf >> 1, h = nf & 1;
                        MMAFP8(acc[mf][nf], a[mf], bb[p][h], bb[p][h + 2]);
                    }
            }
        }
        __syncthreads();   // mainloop smem dead; cs_smem reuse safe

        // positive logit: tiles with tj-ti == 16 hold (i, i+2048) at local (r, r)
        if (tj - ti == 16) {
            #pragma unroll
            for (int mf = 0; mf < 2; mf++)
                #pragma unroll
                for (int h = 0; h < 2; h++) {
                    int gi = i0 + wr * 32 + mf * 16 + (lane >> 2) + h * 8;
                    int pj = gi + HALF_N;
                    #pragma unroll
                    for (int nf = 0; nf < 8; nf++) {
                        int cb = j0 + wc * 64 + nf * 8 + (lane & 3) * 2;
                        if (cb == pj) {
                            float v = acc[mf][nf][2 * h] * LN2S;
                            g_pos[gi] = v; g_pos[pj & (N2 - 1)] = v;
                        }
                        if (cb + 1 == pj) {
                            float v = acc[mf][nf][2 * h + 1] * LN2S;
                            g_pos[gi] = v; g_pos[pj & (N2 - 1)] = v;
                        }
                    }
                }
        }

        // exp (with 1/1024 rescale) in place
        #pragma unroll
        for (int mf = 0; mf < 2; mf++)
            #pragma unroll
            for (int nf = 0; nf < 8; nf++)
                #pragma unroll
                for (int e = 0; e < 4; e++) acc[mf][nf][e] = ex2f(acc[mf][nf][e] * SCI);

        // row sums -> direct slots
        #pragma unroll
        for (int mf = 0; mf < 2; mf++)
            #pragma unroll
            for (int h = 0; h < 2; h++) {
                float rs = 0.0f;
                #pragma unroll
                for (int nf = 0; nf < 8; nf++)
                    rs += acc[mf][nf][2 * h] + acc[mf][nf][2 * h + 1];
                rs += __shfl_xor_sync(0xffffffffu, rs, 1);
                rs += __shfl_xor_sync(0xffffffffu, rs, 2);
                if ((lane & 3) == 0) {
                    int gi = i0 + wr * 32 + mf * 16 + (lane >> 2) + h * 8;
                    g_part[(size_t)gi * NPART + tj * 2 + wc] = rs;
                }
            }

        // col sums -> transposed slots (off-diagonal tiles only)
        if (!diag) {
            float cs[8][2];
            #pragma unroll
            for (int nf = 0; nf < 8; nf++) {
                cs[nf][0] = acc[0][nf][0] + acc[0][nf][2] + acc[1][nf][0] + acc[1][nf][2];
                cs[nf][1] = acc[0][nf][1] + acc[0][nf][3] + acc[1][nf][1] + acc[1][nf][3];
                #pragma unroll
                for (int o = 4; o <= 16; o <<= 1) {
                    cs[nf][0] += __shfl_xor_sync(0xffffffffu, cs[nf][0], o);
                    cs[nf][1] += __shfl_xor_sync(0xffffffffu, cs[nf][1], o);
                }
            }
            if (lane < 4) {
                #pragma unroll
                for (int nf = 0; nf < 8; nf++) {
                    cs_smem[wr * 128 + wc * 64 + nf * 8 + lane * 2]     = cs[nf][0];
                    cs_smem[wr * 128 + wc * 64 + nf * 8 + lane * 2 + 1] = cs[nf][1];
                }
            }
            __syncthreads();
            if (tid < 128) {
                float t = cs_smem[tid] + cs_smem[128 + tid] +
                          cs_smem[256 + tid] + cs_smem[384 + tid];
                g_part[(size_t)(j0 + tid) * NPART + 64 + ti] = t;
            }
        }
        __syncthreads();   // protect cs_smem/stages before next tile's loads
    }
}

// ---------------------------------------------------------------------------
// Kernel 3: per-row lse - pos, block partials; last block reduces + writes mean
// ---------------------------------------------------------------------------
__global__ void __launch_bounds__(256) finalize_kernel(float* __restrict__ out) {
    const float E2 = 7.38905609893065f;   // exp(sim_ii) = e^2
    int t = threadIdx.x;
    int r = blockIdx.x * 256 + t;
    const float4* pr = reinterpret_cast<const float4*>(g_part + (size_t)r * NPART);
    float s = 0.0f;
    #pragma unroll
    for (int i = 0; i < NPART / 4; i++) {
        float4 v = pr[i];
        s += (v.x + v.y) + (v.z + v.w);
    }
    double d = (double)(logf(s - E2) - g_pos[r]);
    #pragma unroll
    for (int o = 16; o; o >>= 1) d += __shfl_xor_sync(0xffffffffu, d, o);
    __shared__ double ws[8];
    __shared__ int last;
    if ((t & 31) == 0) ws[t >> 5] = d;
    __syncthreads();
    if (t < 8) {
        double u = ws[t];
        #pragma unroll
        for (int o = 4; o; o >>= 1) u += __shfl_xor_sync(0xffu, u, o);
        if (t == 0) {
            g_blk[blockIdx.x] = u;
            __threadfence();
            last = (atomicAdd(&g_cnt, 1) == 15);
        }
    }
    __syncthreads();
    if (last && t < 32) {
        double u = (t < 16) ? g_blk[t] : 0.0;
        #pragma unroll
        for (int o = 16; o; o >>= 1) u += __shfl_xor_sync(0xffffffffu, u, o);
        if (t == 0) { out[0] = (float)(u / (double)N2); g_cnt = 0; }
    }
}

// ---------------------------------------------------------------------------
extern "C" void kernel_launch(void* const* d_in, const int* in_sizes, int n_in,
                              void* d_out, int out_size) {
    const float* x = (const float*)d_in[0];
    float* out = (float*)d_out;

    cudaFuncSetAttribute(simexp_mma_kernel,
                         cudaFuncAttributeMaxDynamicSharedMemorySize, SMEM_TOTAL);

    norm_kernel<<<N2 / 16, 256>>>(x);
    simexp_mma_kernel<<<NBLK / 2, 256, SMEM_TOTAL>>>();
    finalize_kernel<<<16, 256>>>(out);
}